// round 15
// baseline (speedup 1.0000x reference)
#include <cuda_runtime.h>
#include <cuda_fp16.h>
#include <mma.h>

#define NN 100000
#define NE 1600000
#define HD 64
#define SCAN_B ((NN + 1023) / 1024)

namespace wm = nvcuda::wmma;

// ---------------- scratch (device globals; no allocation allowed) ----------
__device__ int   g_dc[2 * NN];       // [0:NN)=deg, [NN:2NN)=cnt
__device__ float g_inv[NN];
__device__ int   g_off[NN + 1];
__device__ unsigned long long g_stat[SCAN_B]; // lookback status: (val<<2)|flag
__device__ int   g_blkctr;                    // dynamic block id counter
__device__ int   g_csr_src[NE];
__device__ __half2 g_p16[NN * 32];   // projected neighbor features (half2 pairs)
__device__ float g_h1[NN * HD];      // h1
__device__ float g_h2[NN * HD];      // h2
// per-node tables: 16 x uint4 per node; as uint2[32]:
// idx j = {We-pair(feats 2j,2j+1) , Wl-pair} interleaved
__device__ uint4 g_srct[NN * 16];
__device__ uint4 g_dstt[NN * 16];

__device__ __forceinline__ float tanh_fast(float x) {
    float y;
    asm("tanh.approx.f32 %0, %1;" : "=f"(y) : "f"(x));
    return y;
}
#define H2(u) (*(__half2*)&(u))

// ---------------- fused: degree histogram + p1 projection -------------------
#define PROJ_B ((NN * 32 + 255) / 256)
#define DEG_B  ((NE + 255) / 256)
__global__ void k_dp(const int* __restrict__ dst, const float* __restrict__ nf,
                     const float* __restrict__ W) {
    int bid = blockIdx.x;
    int tid = threadIdx.x;
    if (bid < PROJ_B) {
        __shared__ float sW[4 * HD];
        sW[tid] = W[tid];
        __syncthreads();
        int idx = bid * 256 + tid;
        if (idx >= NN * 32) return;
        int n = idx >> 5, j = idx & 31;
        const float* r = &nf[n * 4];
        float r0 = r[0], r1 = r[1], r2 = r[2], r3 = r[3];
        float v0 = r0 * sW[2*j]   + r1 * sW[64 + 2*j]   + r2 * sW[128 + 2*j]   + r3 * sW[192 + 2*j];
        float v1 = r0 * sW[2*j+1] + r1 * sW[64 + 2*j+1] + r2 * sW[128 + 2*j+1] + r3 * sW[192 + 2*j+1];
        g_p16[idx] = __floats2half2_rn(v0, v1);
    } else {
        int e = (bid - PROJ_B) * 256 + tid;
        if (e < NE) atomicAdd(&g_dc[dst[e]], 1);
    }
}

// -------- single-pass exclusive scan (decoupled lookback) + inv -------------
__global__ void k_scan() {
    __shared__ int sh[1024];
    __shared__ int sbid;
    __shared__ int sprefix;
    int tid = threadIdx.x;
    if (tid == 0) sbid = atomicAdd(&g_blkctr, 1);
    __syncthreads();
    int bid = sbid;
    int i = bid * 1024 + tid;
    int v = (i < NN) ? g_dc[i] : 0;
    sh[tid] = v;
    __syncthreads();
    for (int o = 1; o < 1024; o <<= 1) {
        int t = (tid >= o) ? sh[tid - o] : 0;
        __syncthreads();
        sh[tid] += t;
        __syncthreads();
    }
    int incl = sh[tid];
    int agg  = sh[1023];
    if (tid == 0) {
        if (bid == 0) {
            atomicExch(&g_stat[0], ((unsigned long long)agg << 2) | 2ull);
            sprefix = 0;
        } else {
            // publish aggregate first
            atomicExch(&g_stat[bid], ((unsigned long long)agg << 2) | 1ull);
            // lookback
            int runp = 0;
            int j = bid - 1;
            while (true) {
                unsigned long long s = atomicAdd(&g_stat[j], 0ull);
                int flag = (int)(s & 3ull);
                if (flag == 2) { runp += (int)(s >> 2); break; }
                if (flag == 1) { runp += (int)(s >> 2); j--; }
            }
            atomicExch(&g_stat[bid],
                       (((unsigned long long)(runp + agg)) << 2) | 2ull);
            sprefix = runp;
        }
        if (bid == SCAN_B - 1) g_off[NN] = sprefix + agg;
    }
    __syncthreads();
    int pre = sprefix;
    if (i < NN) {
        g_off[i] = pre + incl - v;          // exclusive
        g_inv[i] = 1.0f / (float)(v > 0 ? v : 1);
    }
}

// ---------------- CSR scatter ------------------------------------------------
__global__ void k_scatter(const int* __restrict__ src, const int* __restrict__ dst) {
    int e = blockIdx.x * blockDim.x + threadIdx.x;
    if (e < NE) {
        int d = dst[e];
        int pos = atomicAdd(&g_dc[NN + d], 1);
        g_csr_src[g_off[d] + pos] = src[e];
    }
}

// ---------------- SAGE layer 1 (MLP=16/8/4 gathers) --------------------------
__global__ void k_sage1(const float* __restrict__ nf, const float* __restrict__ Ws,
                        const float* __restrict__ b) {
    __shared__ float sW[4 * HD];
    int tid = threadIdx.x;
    sW[tid] = Ws[tid];
    __syncthreads();
    int n = blockIdx.x * 8 + (tid >> 5);
    int l = tid & 31;
    if (n >= NN) return;
    int beg = g_off[n], end = g_off[n + 1];
    float ax = 0.f, ay = 0.f;
    int j = beg;
    for (; j + 16 <= end; j += 16) {
        int si[16];
#pragma unroll
        for (int t = 0; t < 16; t++) si[t] = g_csr_src[j + t];
        float2 q[16];
#pragma unroll
        for (int t = 0; t < 16; t++) q[t] = __half22float2(g_p16[si[t] * 32 + l]);
        float a0 = 0.f, a1 = 0.f;
#pragma unroll
        for (int t = 0; t < 16; t++) { a0 += q[t].x; a1 += q[t].y; }
        ax += a0; ay += a1;
    }
    for (; j + 8 <= end; j += 8) {
        int s0 = g_csr_src[j],     s1 = g_csr_src[j + 1];
        int s2 = g_csr_src[j + 2], s3 = g_csr_src[j + 3];
        int s4 = g_csr_src[j + 4], s5 = g_csr_src[j + 5];
        int s6 = g_csr_src[j + 6], s7 = g_csr_src[j + 7];
        float2 q0 = __half22float2(g_p16[s0 * 32 + l]);
        float2 q1 = __half22float2(g_p16[s1 * 32 + l]);
        float2 q2 = __half22float2(g_p16[s2 * 32 + l]);
        float2 q3 = __half22float2(g_p16[s3 * 32 + l]);
        float2 q4 = __half22float2(g_p16[s4 * 32 + l]);
        float2 q5 = __half22float2(g_p16[s5 * 32 + l]);
        float2 q6 = __half22float2(g_p16[s6 * 32 + l]);
        float2 q7 = __half22float2(g_p16[s7 * 32 + l]);
        ax += ((q0.x + q1.x) + (q2.x + q3.x)) + ((q4.x + q5.x) + (q6.x + q7.x));
        ay += ((q0.y + q1.y) + (q2.y + q3.y)) + ((q4.y + q5.y) + (q6.y + q7.y));
    }
    for (; j + 4 <= end; j += 4) {
        int s0 = g_csr_src[j],     s1 = g_csr_src[j + 1];
        int s2 = g_csr_src[j + 2], s3 = g_csr_src[j + 3];
        float2 q0 = __half22float2(g_p16[s0 * 32 + l]);
        float2 q1 = __half22float2(g_p16[s1 * 32 + l]);
        float2 q2 = __half22float2(g_p16[s2 * 32 + l]);
        float2 q3 = __half22float2(g_p16[s3 * 32 + l]);
        ax += (q0.x + q1.x) + (q2.x + q3.x);
        ay += (q0.y + q1.y) + (q2.y + q3.y);
    }
    for (; j < end; j++) {
        float2 q = __half22float2(g_p16[g_csr_src[j] * 32 + l]);
        ax += q.x; ay += q.y;
    }
    float iv = g_inv[n];
    const float* r = &nf[n * 4];
    float n0 = r[0], n1 = r[1], n2 = r[2], n3 = r[3];
    float sx = n0*sW[2*l]   + n1*sW[64+2*l]   + n2*sW[128+2*l]   + n3*sW[192+2*l];
    float sy = n0*sW[2*l+1] + n1*sW[64+2*l+1] + n2*sW[128+2*l+1] + n3*sW[192+2*l+1];
    float2 o;
    o.x = fmaxf(sx + ax * iv + b[2*l],     0.f);
    o.y = fmaxf(sy + ay * iv + b[2*l+1],   0.f);
    *(float2*)&g_h1[(size_t)n * HD + 2*l] = o;
}

// ================= WMMA GEMM stages (fp16 in, fp32 accum) ===================

// ---- dual: p16 = X@Wn (half2), outf = X@Ws (fp32), no bias ----------------
__global__ void k_wdual(const float* __restrict__ in, const float* __restrict__ Wn,
                        const float* __restrict__ Ws, float* __restrict__ outf) {
    __shared__ __align__(32) __half Xh[128 * HD];
    __shared__ __align__(32) __half WA[HD * HD];
    __shared__ __align__(32) __half WB[HD * HD];
    __shared__ float scr[8][256];
    int tid = threadIdx.x, w = tid >> 5, lane = tid & 31;
    int nbase = blockIdx.x * 128;
    int base = nbase * HD;
    for (int t = tid; t < 128 * HD; t += 256) {
        int gi = base + t;
        Xh[t] = (gi < NN * HD) ? __float2half(in[gi]) : __half(0.f);
    }
    for (int t = tid; t < HD * HD; t += 256) {
        WA[t] = __float2half(Wn[t]);
        WB[t] = __float2half(Ws[t]);
    }
    __syncthreads();
    int r0 = w * 16;
#pragma unroll
    for (int nt = 0; nt < 4; nt++) {
        wm::fragment<wm::accumulator, 16, 16, 16, float> accA, accB;
        wm::fill_fragment(accA, 0.f);
        wm::fill_fragment(accB, 0.f);
#pragma unroll
        for (int kt = 0; kt < 4; kt++) {
            wm::fragment<wm::matrix_a, 16, 16, 16, __half, wm::row_major> a;
            wm::fragment<wm::matrix_b, 16, 16, 16, __half, wm::row_major> bA, bB;
            wm::load_matrix_sync(a, Xh + r0 * HD + kt * 16, HD);
            wm::load_matrix_sync(bA, WA + kt * 16 * HD + nt * 16, HD);
            wm::load_matrix_sync(bB, WB + kt * 16 * HD + nt * 16, HD);
            wm::mma_sync(accA, a, bA, accA);
            wm::mma_sync(accB, a, bB, accB);
        }
        wm::store_matrix_sync(scr[w], accB, 16, wm::mem_row_major);
        __syncwarp();
        for (int t = lane; t < 256; t += 32) {
            int row = t >> 4, col = t & 15;
            int n = nbase + r0 + row;
            if (n < NN) outf[(size_t)n * HD + nt * 16 + col] = scr[w][t];
        }
        __syncwarp();
        wm::store_matrix_sync(scr[w], accA, 16, wm::mem_row_major);
        __syncwarp();
        for (int t = lane; t < 128; t += 32) {
            int row = t >> 3, cp = t & 7;
            int n = nbase + r0 + row;
            if (n < NN)
                g_p16[(size_t)n * 32 + nt * 8 + cp] =
                    __floats2half2_rn(scr[w][row * 16 + 2 * cp], scr[w][row * 16 + 2 * cp + 1]);
        }
        __syncwarp();
    }
}

// ---- fused: hp = relu(h2@Wnp + bnp) in smem, then both role table GEMMs ----
__global__ void k_wfuse(const float* __restrict__ h2in, const float* __restrict__ Wnp,
                        const float* __restrict__ bnp,
                        const float* __restrict__ We1, const float* __restrict__ Wl1,
                        unsigned int* __restrict__ utab_s, unsigned int* __restrict__ utab_d) {
    __shared__ __align__(32) __half Xh[128 * HD];   // phase1 A operand / phase2 scratch
    __shared__ __align__(32) __half Yh[128 * HD];   // hp tile (phase2 A operand)
    __shared__ __align__(32) __half WA[HD * HD];
    __shared__ __align__(32) __half WB[HD * HD];    // phase1 scratch / phase2 Wl weights
    int tid = threadIdx.x, w = tid >> 5, lane = tid & 31;
    int nbase = blockIdx.x * 128;
    int base = nbase * HD;
    for (int t = tid; t < 128 * HD; t += 256) {
        int gi = base + t;
        Xh[t] = (gi < NN * HD) ? __float2half(h2in[gi]) : __half(0.f);
    }
    for (int t = tid; t < HD * HD; t += 256) WA[t] = __float2half(Wnp[t]);
    __syncthreads();

    int r0 = w * 16;
    // ---- phase 1: hp tile into Yh ----
    {
        float* scr1 = (float*)WB;
#pragma unroll
        for (int nt = 0; nt < 4; nt++) {
            wm::fragment<wm::accumulator, 16, 16, 16, float> acc;
            wm::fill_fragment(acc, 0.f);
#pragma unroll
            for (int kt = 0; kt < 4; kt++) {
                wm::fragment<wm::matrix_a, 16, 16, 16, __half, wm::row_major> a;
                wm::fragment<wm::matrix_b, 16, 16, 16, __half, wm::row_major> b;
                wm::load_matrix_sync(a, Xh + r0 * HD + kt * 16, HD);
                wm::load_matrix_sync(b, WA + kt * 16 * HD + nt * 16, HD);
                wm::mma_sync(acc, a, b, acc);
            }
            wm::store_matrix_sync(scr1 + w * 256, acc, 16, wm::mem_row_major);
            __syncwarp();
            for (int t = lane; t < 256; t += 32) {
                int row = t >> 4, col = t & 15;
                float v = scr1[w * 256 + t] + __ldg(&bnp[nt * 16 + col]);
                Yh[(r0 + row) * HD + nt * 16 + col] = __float2half(fmaxf(v, 0.f));
            }
            __syncwarp();
        }
    }
    __syncthreads();

    // ---- phase 2: two roles, tables from Yh ----
    float* scr2 = (float*)Xh;
    for (int role = 0; role < 2; role++) {
        const float* Wa = We1 + role * 64 * HD;
        const float* Wb = Wl1 + role * 64 * HD;
        unsigned int* utab = role ? utab_d : utab_s;
        for (int t = tid; t < HD * HD; t += 256) {
            WA[t] = __float2half(Wa[t]);
            WB[t] = __float2half(Wb[t]);
        }
        __syncthreads();
#pragma unroll
        for (int nt = 0; nt < 4; nt++) {
            wm::fragment<wm::accumulator, 16, 16, 16, float> accA, accB;
            wm::fill_fragment(accA, 0.f);
            wm::fill_fragment(accB, 0.f);
#pragma unroll
            for (int kt = 0; kt < 4; kt++) {
                wm::fragment<wm::matrix_a, 16, 16, 16, __half, wm::row_major> a;
                wm::fragment<wm::matrix_b, 16, 16, 16, __half, wm::row_major> bA, bB;
                wm::load_matrix_sync(a, Yh + r0 * HD + kt * 16, HD);
                wm::load_matrix_sync(bA, WA + kt * 16 * HD + nt * 16, HD);
                wm::load_matrix_sync(bB, WB + kt * 16 * HD + nt * 16, HD);
                wm::mma_sync(accA, a, bA, accA);
                wm::mma_sync(accB, a, bB, accB);
            }
            wm::store_matrix_sync(scr2 + w * 256, accA, 16, wm::mem_row_major);
            __syncwarp();
            for (int t = lane; t < 128; t += 32) {
                int row = t >> 3, cp = t & 7;
                int n = nbase + r0 + row;
                if (n < NN) {
                    __half2 h = __floats2half2_rn(scr2[w * 256 + row * 16 + 2 * cp],
                                                  scr2[w * 256 + row * 16 + 2 * cp + 1]);
                    utab[((size_t)n * 32 + nt * 8 + cp) * 2] = *(unsigned int*)&h;
                }
            }
            __syncwarp();
            wm::store_matrix_sync(scr2 + w * 256, accB, 16, wm::mem_row_major);
            __syncwarp();
            for (int t = lane; t < 128; t += 32) {
                int row = t >> 3, cp = t & 7;
                int n = nbase + r0 + row;
                if (n < NN) {
                    __half2 h = __floats2half2_rn(scr2[w * 256 + row * 16 + 2 * cp],
                                                  scr2[w * 256 + row * 16 + 2 * cp + 1]);
                    utab[((size_t)n * 32 + nt * 8 + cp) * 2 + 1] = *(unsigned int*)&h;
                }
            }
            __syncwarp();
        }
        __syncthreads();
    }
}

// ---------------- SAGE layer 2 combine (MLP=16/8/4 gathers) ------------------
__global__ void k_sage2b(const float* __restrict__ b) {
    int tid = threadIdx.x;
    int n = blockIdx.x * 8 + (tid >> 5);
    int l = tid & 31;
    if (n >= NN) return;
    int beg = g_off[n], end = g_off[n + 1];
    float ax = 0.f, ay = 0.f;
    int j = beg;
    for (; j + 16 <= end; j += 16) {
        int si[16];
#pragma unroll
        for (int t = 0; t < 16; t++) si[t] = g_csr_src[j + t];
        float2 q[16];
#pragma unroll
        for (int t = 0; t < 16; t++) q[t] = __half22float2(g_p16[si[t] * 32 + l]);
        float a0 = 0.f, a1 = 0.f;
#pragma unroll
        for (int t = 0; t < 16; t++) { a0 += q[t].x; a1 += q[t].y; }
        ax += a0; ay += a1;
    }
    for (; j + 8 <= end; j += 8) {
        int s0 = g_csr_src[j],     s1 = g_csr_src[j + 1];
        int s2 = g_csr_src[j + 2], s3 = g_csr_src[j + 3];
        int s4 = g_csr_src[j + 4], s5 = g_csr_src[j + 5];
        int s6 = g_csr_src[j + 6], s7 = g_csr_src[j + 7];
        float2 q0 = __half22float2(g_p16[s0 * 32 + l]);
        float2 q1 = __half22float2(g_p16[s1 * 32 + l]);
        float2 q2 = __half22float2(g_p16[s2 * 32 + l]);
        float2 q3 = __half22float2(g_p16[s3 * 32 + l]);
        float2 q4 = __half22float2(g_p16[s4 * 32 + l]);
        float2 q5 = __half22float2(g_p16[s5 * 32 + l]);
        float2 q6 = __half22float2(g_p16[s6 * 32 + l]);
        float2 q7 = __half22float2(g_p16[s7 * 32 + l]);
        ax += ((q0.x + q1.x) + (q2.x + q3.x)) + ((q4.x + q5.x) + (q6.x + q7.x));
        ay += ((q0.y + q1.y) + (q2.y + q3.y)) + ((q4.y + q5.y) + (q6.y + q7.y));
    }
    for (; j + 4 <= end; j += 4) {
        int s0 = g_csr_src[j],     s1 = g_csr_src[j + 1];
        int s2 = g_csr_src[j + 2], s3 = g_csr_src[j + 3];
        float2 q0 = __half22float2(g_p16[s0 * 32 + l]);
        float2 q1 = __half22float2(g_p16[s1 * 32 + l]);
        float2 q2 = __half22float2(g_p16[s2 * 32 + l]);
        float2 q3 = __half22float2(g_p16[s3 * 32 + l]);
        ax += (q0.x + q1.x) + (q2.x + q3.x);
        ay += (q0.y + q1.y) + (q2.y + q3.y);
    }
    for (; j < end; j++) {
        float2 q = __half22float2(g_p16[g_csr_src[j] * 32 + l]);
        ax += q.x; ay += q.y;
    }
    float iv = g_inv[n];
    float2 t = *(const float2*)&g_h2[(size_t)n * HD + 2 * l];
    float2 o;
    o.x = fmaxf(t.x + ax * iv + b[2 * l],     0.f);
    o.y = fmaxf(t.y + ay * iv + b[2 * l + 1], 0.f);
    *(float2*)&g_h2[(size_t)n * HD + 2 * l] = o;
}

// ------- edge kernel: 8 lanes/edge, 4 edges/warp, 2-deep table pipeline ------
__global__ void __launch_bounds__(256, 2) k_edge(
                       const int* __restrict__ src, const int* __restrict__ dst,
                       const float* __restrict__ ef,
                       const float* __restrict__ We1, const float* __restrict__ be1,
                       const float* __restrict__ We2, const float* __restrict__ be2,
                       const float* __restrict__ Wl1, const float* __restrict__ bl1,
                       const float* __restrict__ Wl2, const float* __restrict__ bl2,
                       float* __restrict__ out) {
    int tid = threadIdx.x;
    int l = tid & 31;
    int li = l & 7;             // lane within 8-lane edge group
    int g = l >> 3;             // which of the 4 edges
    int base = l & 24;          // shfl base for my group
    int warp = (blockIdx.x * blockDim.x + tid) >> 5;
    int nw = (gridDim.x * blockDim.x) >> 5;
    int stepE = 4 * nw;

    // per-lane constants: feats 8*li .. 8*li+7
    __half2 weh[5][4], wlh[5][4];
#pragma unroll
    for (int k = 0; k < 5; k++) {
        float4 a0 = *(const float4*)&We1[(128 + k) * HD + 8 * li];
        float4 a1 = *(const float4*)&We1[(128 + k) * HD + 8 * li + 4];
        float4 b0 = *(const float4*)&Wl1[(128 + k) * HD + 8 * li];
        float4 b1 = *(const float4*)&Wl1[(128 + k) * HD + 8 * li + 4];
        weh[k][0] = __floats2half2_rn(a0.x, a0.y);
        weh[k][1] = __floats2half2_rn(a0.z, a0.w);
        weh[k][2] = __floats2half2_rn(a1.x, a1.y);
        weh[k][3] = __floats2half2_rn(a1.z, a1.w);
        wlh[k][0] = __floats2half2_rn(b0.x, b0.y);
        wlh[k][1] = __floats2half2_rn(b0.z, b0.w);
        wlh[k][2] = __floats2half2_rn(b1.x, b1.y);
        wlh[k][3] = __floats2half2_rn(b1.z, b1.w);
    }
    float4 be1a = *(const float4*)&be1[8 * li];
    float4 be1b = *(const float4*)&be1[8 * li + 4];
    __half2 be1h[4];
    be1h[0] = __floats2half2_rn(be1a.x, be1a.y);
    be1h[1] = __floats2half2_rn(be1a.z, be1a.w);
    be1h[2] = __floats2half2_rn(be1b.x, be1b.y);
    be1h[3] = __floats2half2_rn(be1b.z, be1b.w);
    float4 bl1a = *(const float4*)&bl1[8 * li];
    float4 bl1b = *(const float4*)&bl1[8 * li + 4];
    float4 we2a = *(const float4*)&We2[8 * li];
    float4 we2b = *(const float4*)&We2[8 * li + 4];
    float4 wl2a = *(const float4*)&Wl2[8 * li];
    float4 wl2b = *(const float4*)&Wl2[8 * li + 4];
    float be2v = be2[0], bl2v = bl2[0];

    // ---- pipeline prologue ----
    int e0 = warp * 4 + g;
    int sCur = 0, dCur = 0;
    float efA = 0.f;
    if (e0 < NE) {
        sCur = __ldg(&src[e0]);
        dCur = __ldg(&dst[e0]);
        efA = (li < 5) ? __ldg(&ef[(size_t)e0 * 5 + li]) : 0.f;
    }
    uint4 cs0, cs1, cd0, cd1;
    {
        const uint4* ps = &g_srct[(size_t)sCur * 16];
        const uint4* pd = &g_dstt[(size_t)dCur * 16];
        cs0 = ps[2 * li];  cs1 = ps[2 * li + 1];
        cd0 = pd[2 * li];  cd1 = pd[2 * li + 1];
    }
    int e1 = e0 + stepE;
    int sNxt = 0, dNxt = 0;
    float efB = 0.f;
    if (e1 < NE) {
        sNxt = __ldg(&src[e1]);
        dNxt = __ldg(&dst[e1]);
        efB = (li < 5) ? __ldg(&ef[(size_t)e1 * 5 + li]) : 0.f;
    }

    for (int eb = warp * 4; eb < NE; eb += stepE) {
        int ecur = eb + g;
        // 1) issue next-iteration table gathers (indices already resident)
        uint4 ns0, ns1, nd0, nd1;
        {
            const uint4* ps = &g_srct[(size_t)sNxt * 16];
            const uint4* pd = &g_dstt[(size_t)dNxt * 16];
            ns0 = ps[2 * li];  ns1 = ps[2 * li + 1];
            nd0 = pd[2 * li];  nd1 = pd[2 * li + 1];
        }
        // 2) issue next-next index loads
        int e2 = ecur + 2 * stepE;
        int sNN = 0, dNN = 0;
        float efC = 0.f;
        if (e2 < NE) {
            sNN = __ldg(&src[e2]);
            dNN = __ldg(&dst[e2]);
            efC = (li < 5) ? __ldg(&ef[(size_t)e2 * 5 + li]) : 0.f;
        }

        // 3) compute with current tables (cs*, cd*, efA)
        __half2 efh = __float2half2_rn(efA);
        __half2 tW0 = __hadd2(__hadd2(H2(cs0.x), H2(cd0.x)), be1h[0]);
        __half2 tW1 = __hadd2(__hadd2(H2(cs0.z), H2(cd0.z)), be1h[1]);
        __half2 tW2 = __hadd2(__hadd2(H2(cs1.x), H2(cd1.x)), be1h[2]);
        __half2 tW3 = __hadd2(__hadd2(H2(cs1.z), H2(cd1.z)), be1h[3]);
        __half2 tL0 = __hadd2(H2(cs0.y), H2(cd0.y));
        __half2 tL1 = __hadd2(H2(cs0.w), H2(cd0.w));
        __half2 tL2 = __hadd2(H2(cs1.y), H2(cd1.y));
        __half2 tL3 = __hadd2(H2(cs1.w), H2(cd1.w));

        unsigned int efu = *(unsigned int*)&efh;
        unsigned int eku = __shfl_sync(0xffffffffu, efu, base);
        __half2 ekh = *(__half2*)&eku;
        __half2 cW0 = __hmul2(ekh, weh[0][0]);
        __half2 cW1 = __hmul2(ekh, weh[0][1]);
        __half2 cW2 = __hmul2(ekh, weh[0][2]);
        __half2 cW3 = __hmul2(ekh, weh[0][3]);
        __half2 cL0 = __hmul2(ekh, wlh[0][0]);
        __half2 cL1 = __hmul2(ekh, wlh[0][1]);
        __half2 cL2 = __hmul2(ekh, wlh[0][2]);
        __half2 cL3 = __hmul2(ekh, wlh[0][3]);
#pragma unroll
        for (int k = 1; k < 5; k++) {
            eku = __shfl_sync(0xffffffffu, efu, base + k);
            ekh = *(__half2*)&eku;
            cW0 = __hfma2(ekh, weh[k][0], cW0);
            cW1 = __hfma2(ekh, weh[k][1], cW1);
            cW2 = __hfma2(ekh, weh[k][2], cW2);
            cW3 = __hfma2(ekh, weh[k][3], cW3);
            cL0 = __hfma2(ekh, wlh[k][0], cL0);
            cL1 = __hfma2(ekh, wlh[k][1], cL1);
            cL2 = __hfma2(ekh, wlh[k][2], cL2);
            cL3 = __hfma2(ekh, wlh[k][3], cL3);
        }
        float2 u0 = __half22float2(tW0), w0 = __half22float2(cW0);
        float2 u1 = __half22float2(tW1), w1 = __half22float2(cW1);
        float2 u2 = __half22float2(tW2), w2 = __half22float2(cW2);
        float2 u3 = __half22float2(tW3), w3 = __half22float2(cW3);
        float part = tanh_fast(u0.x + w0.x) * we2a.x + tanh_fast(u0.y + w0.y) * we2a.y
                   + tanh_fast(u1.x + w1.x) * we2a.z + tanh_fast(u1.y + w1.y) * we2a.w
                   + tanh_fast(u2.x + w2.x) * we2b.x + tanh_fast(u2.y + w2.y) * we2b.y
                   + tanh_fast(u3.x + w3.x) * we2b.z + tanh_fast(u3.y + w3.y) * we2b.w;
#pragma unroll
        for (int o = 4; o > 0; o >>= 1) part += __shfl_xor_sync(0xffffffffu, part, o);
        float wgt = 1.f / (1.f + __expf(-(part + be2v)));

        float2 v0 = __half22float2(tL0), x0 = __half22float2(cL0);
        float2 v1 = __half22float2(tL1), x1 = __half22float2(cL1);
        float2 v2 = __half22float2(tL2), x2 = __half22float2(cL2);
        float2 v3 = __half22float2(tL3), x3 = __half22float2(cL3);
        float o0 = fmaxf(fmaf(wgt, v0.x + x0.x, bl1a.x), 0.f);
        float o1 = fmaxf(fmaf(wgt, v0.y + x0.y, bl1a.y), 0.f);
        float o2 = fmaxf(fmaf(wgt, v1.x + x1.x, bl1a.z), 0.f);
        float o3 = fmaxf(fmaf(wgt, v1.y + x1.y, bl1a.w), 0.f);
        float o4 = fmaxf(fmaf(wgt, v2.x + x2.x, bl1b.x), 0.f);
        float o5 = fmaxf(fmaf(wgt, v2.y + x2.y, bl1b.y), 0.f);
        float o6 = fmaxf(fmaf(wgt, v3.x + x3.x, bl1b.z), 0.f);
        float o7 = fmaxf(fmaf(wgt, v3.y + x3.y, bl1b.w), 0.f);
        float p2 = (o0 * wl2a.x + o1 * wl2a.y) + (o2 * wl2a.z + o3 * wl2a.w)
                 + (o4 * wl2b.x + o5 * wl2b.y) + (o6 * wl2b.z + o7 * wl2b.w);
#pragma unroll
        for (int o = 4; o > 0; o >>= 1) p2 += __shfl_xor_sync(0xffffffffu, p2, o);
        if (li == 0) out[ecur] = p2 + bl2v;

        // 4) rotate pipeline
        cs0 = ns0; cs1 = ns1; cd0 = nd0; cd1 = nd1;
        efA = efB; efB = efC;
        sNxt = sNN; dNxt = dNN;
    }
}

// ---------------- launch -----------------------------------------------------
extern "C" void kernel_launch(void* const* d_in, const int* in_sizes, int n_in,
                              void* d_out, int out_size) {
    const float* node_feat = (const float*)d_in[0];
    const float* edge_feat = (const float*)d_in[1];
    const int*   src       = (const int*)d_in[2];
    const int*   dst       = (const int*)d_in[3];
    const float* W1s = (const float*)d_in[4];
    const float* W1n = (const float*)d_in[5];
    const float* b1  = (const float*)d_in[6];
    const float* W2s = (const float*)d_in[7];
    const float* W2n = (const float*)d_in[8];
    const float* b2  = (const float*)d_in[9];
    const float* Wnp = (const float*)d_in[10];
    const float* bnp = (const float*)d_in[11];
    const float* We1 = (const float*)d_in[12];
    const float* be1 = (const float*)d_in[13];
    const float* We2 = (const float*)d_in[14];
    const float* be2 = (const float*)d_in[15];
    const float* Wl1 = (const float*)d_in[16];
    const float* bl1 = (const float*)d_in[17];
    const float* Wl2 = (const float*)d_in[18];
    const float* bl2 = (const float*)d_in[19];
    float* out = (float*)d_out;

    float *ph1, *ph2;
    void *pst, *pdt, *pdc, *pstat, *pctr;
    cudaGetSymbolAddress((void**)&ph1, g_h1);
    cudaGetSymbolAddress((void**)&ph2, g_h2);
    cudaGetSymbolAddress(&pst, g_srct);
    cudaGetSymbolAddress(&pdt, g_dstt);
    cudaGetSymbolAddress(&pdc, g_dc);
    cudaGetSymbolAddress(&pstat, g_stat);
    cudaGetSymbolAddress(&pctr, g_blkctr);

    int nblk = (NN + 7) / 8;          // warp-per-node kernels
    int wblk = (NN + 127) / 128;      // WMMA kernels (128 nodes/block)

    cudaMemsetAsync(pdc, 0, 2 * NN * sizeof(int));
    cudaMemsetAsync(pstat, 0, SCAN_B * sizeof(unsigned long long));
    cudaMemsetAsync(pctr, 0, sizeof(int));
    // fused: p1 projection + degree histogram (independent work, one launch)
    k_dp<<<PROJ_B + DEG_B, 256>>>(dst, node_feat, W1n);
    // single-pass decoupled-lookback exclusive scan + inv
    k_scan<<<SCAN_B, 1024>>>();
    k_scatter<<<(NE + 255) / 256, 256>>>(src, dst);

    // Layer 1
    k_sage1<<<nblk, 256>>>(node_feat, W1s, b1);

    // Layer 2: p2 = h1@W2n (half2) AND h1@W2s (fp32) via WMMA, then combine
    k_wdual<<<wblk, 256>>>(ph1, W2n, W2s, ph2);
    k_sage2b<<<nblk, 256>>>(b2);

    // fused: hp = relu(h2@Wnp+bnp) in smem, then both role tables
    k_wfuse<<<wblk, 256>>>(ph2, Wnp, bnp, We1, Wl1,
                           (unsigned int*)pst, (unsigned int*)pdt);

    // persistent fused edge stage: 8 lanes/edge, 4 edges/warp, 2-deep pipeline
    // grid = exact 2-blocks/SM residency (148 SMs x 2)
    k_edge<<<296, 256>>>(src, dst, edge_feat,
                         We1, be1, We2, be2, Wl1, bl1, Wl2, bl2, out);
}

// round 16
// speedup vs baseline: 1.0148x; 1.0148x over previous
#include <cuda_runtime.h>
#include <cuda_fp16.h>
#include <mma.h>

#define NN 100000
#define NE 1600000
#define HD 64

namespace wm = nvcuda::wmma;

// ---------------- scratch (device globals; no allocation allowed) ----------
__device__ int   g_dc[NN];           // deg, then reused as scatter cursor
__device__ float g_inv[NN];
__device__ int   g_off[NN + 1];
__device__ int   g_bsum[128];
__device__ int   g_csr_src[NE];
__device__ __half2 g_p16[NN * 32];   // projected neighbor features (half2 pairs)
__device__ float g_h1[NN * HD];      // h1
__device__ float g_h2[NN * HD];      // h2
// per-node tables: 16 x uint4 per node; as uint2[32]:
// idx j = {We-pair(feats 2j,2j+1) , Wl-pair} interleaved
__device__ uint4 g_srct[NN * 16];
__device__ uint4 g_dstt[NN * 16];

__device__ __forceinline__ float tanh_fast(float x) {
    float y;
    asm("tanh.approx.f32 %0, %1;" : "=f"(y) : "f"(x));
    return y;
}
#define H2(u) (*(__half2*)&(u))

// ---------------- fused: degree histogram + p1 projection -------------------
#define PROJ_B ((NN * 32 + 255) / 256)
#define DEG_B  ((NE + 255) / 256)
__global__ void k_dp(const int* __restrict__ dst, const float* __restrict__ nf,
                     const float* __restrict__ W) {
    int bid = blockIdx.x;
    int tid = threadIdx.x;
    if (bid < PROJ_B) {
        __shared__ float sW[4 * HD];
        sW[tid] = W[tid];
        __syncthreads();
        int idx = bid * 256 + tid;
        if (idx >= NN * 32) return;
        int n = idx >> 5, j = idx & 31;
        const float* r = &nf[n * 4];
        float r0 = r[0], r1 = r[1], r2 = r[2], r3 = r[3];
        float v0 = r0 * sW[2*j]   + r1 * sW[64 + 2*j]   + r2 * sW[128 + 2*j]   + r3 * sW[192 + 2*j];
        float v1 = r0 * sW[2*j+1] + r1 * sW[64 + 2*j+1] + r2 * sW[128 + 2*j+1] + r3 * sW[192 + 2*j+1];
        g_p16[idx] = __floats2half2_rn(v0, v1);
    } else {
        int e = (bid - PROJ_B) * 256 + tid;
        if (e < NE) atomicAdd(&g_dc[dst[e]], 1);
    }
}

// ---------------- exclusive scan (3 kernels) --------------------------------
__global__ void k_scan1() {
    __shared__ int sh[1024];
    int tid = threadIdx.x;
    int i = blockIdx.x * 1024 + tid;
    int v = (i < NN) ? g_dc[i] : 0;
    sh[tid] = v;
    __syncthreads();
    for (int o = 1; o < 1024; o <<= 1) {
        int t = (tid >= o) ? sh[tid - o] : 0;
        __syncthreads();
        sh[tid] += t;
        __syncthreads();
    }
    if (i < NN) g_off[i] = sh[tid] - v;      // exclusive within block
    if (tid == 1023) g_bsum[blockIdx.x] = sh[1023];
}

__global__ void k_scan2(int nb) {
    __shared__ int sh[128];
    int tid = threadIdx.x;
    int v = (tid < nb) ? g_bsum[tid] : 0;
    sh[tid] = v;
    __syncthreads();
    for (int o = 1; o < 128; o <<= 1) {
        int t = (tid >= o) ? sh[tid - o] : 0;
        __syncthreads();
        sh[tid] += t;
        __syncthreads();
    }
    g_bsum[tid] = sh[tid] - v;
    if (tid == 127) g_off[NN] = sh[127];
}

// finalizes offsets; writes inv; re-seeds g_dc as the scatter cursor
__global__ void k_scan3() {
    int i = blockIdx.x * blockDim.x + threadIdx.x;
    if (i < NN) {
        int off = g_off[i] + g_bsum[i >> 10];
        int d = g_dc[i];
        g_off[i] = off;
        g_dc[i] = off;                       // scatter cursor
        g_inv[i] = 1.0f / (float)(d > 0 ? d : 1);
    }
}

// ---------------- CSR scatter (cursor in g_dc) -------------------------------
__global__ void k_scatter(const int* __restrict__ src, const int* __restrict__ dst) {
    int e = blockIdx.x * blockDim.x + threadIdx.x;
    if (e < NE) {
        int pos = atomicAdd(&g_dc[dst[e]], 1);
        g_csr_src[pos] = src[e];
    }
}

// ---------------- SAGE layer 1 (MLP=16/8/4 gathers) --------------------------
__global__ void k_sage1(const float* __restrict__ nf, const float* __restrict__ Ws,
                        const float* __restrict__ b) {
    __shared__ float sW[4 * HD];
    int tid = threadIdx.x;
    sW[tid] = Ws[tid];
    __syncthreads();
    int n = blockIdx.x * 8 + (tid >> 5);
    int l = tid & 31;
    if (n >= NN) return;
    int beg = g_off[n], end = g_off[n + 1];
    float ax = 0.f, ay = 0.f;
    int j = beg;
    for (; j + 16 <= end; j += 16) {
        int si[16];
#pragma unroll
        for (int t = 0; t < 16; t++) si[t] = g_csr_src[j + t];
        float2 q[16];
#pragma unroll
        for (int t = 0; t < 16; t++) q[t] = __half22float2(g_p16[si[t] * 32 + l]);
        float a0 = 0.f, a1 = 0.f;
#pragma unroll
        for (int t = 0; t < 16; t++) { a0 += q[t].x; a1 += q[t].y; }
        ax += a0; ay += a1;
    }
    for (; j + 8 <= end; j += 8) {
        int s0 = g_csr_src[j],     s1 = g_csr_src[j + 1];
        int s2 = g_csr_src[j + 2], s3 = g_csr_src[j + 3];
        int s4 = g_csr_src[j + 4], s5 = g_csr_src[j + 5];
        int s6 = g_csr_src[j + 6], s7 = g_csr_src[j + 7];
        float2 q0 = __half22float2(g_p16[s0 * 32 + l]);
        float2 q1 = __half22float2(g_p16[s1 * 32 + l]);
        float2 q2 = __half22float2(g_p16[s2 * 32 + l]);
        float2 q3 = __half22float2(g_p16[s3 * 32 + l]);
        float2 q4 = __half22float2(g_p16[s4 * 32 + l]);
        float2 q5 = __half22float2(g_p16[s5 * 32 + l]);
        float2 q6 = __half22float2(g_p16[s6 * 32 + l]);
        float2 q7 = __half22float2(g_p16[s7 * 32 + l]);
        ax += ((q0.x + q1.x) + (q2.x + q3.x)) + ((q4.x + q5.x) + (q6.x + q7.x));
        ay += ((q0.y + q1.y) + (q2.y + q3.y)) + ((q4.y + q5.y) + (q6.y + q7.y));
    }
    for (; j + 4 <= end; j += 4) {
        int s0 = g_csr_src[j],     s1 = g_csr_src[j + 1];
        int s2 = g_csr_src[j + 2], s3 = g_csr_src[j + 3];
        float2 q0 = __half22float2(g_p16[s0 * 32 + l]);
        float2 q1 = __half22float2(g_p16[s1 * 32 + l]);
        float2 q2 = __half22float2(g_p16[s2 * 32 + l]);
        float2 q3 = __half22float2(g_p16[s3 * 32 + l]);
        ax += (q0.x + q1.x) + (q2.x + q3.x);
        ay += (q0.y + q1.y) + (q2.y + q3.y);
    }
    for (; j < end; j++) {
        float2 q = __half22float2(g_p16[g_csr_src[j] * 32 + l]);
        ax += q.x; ay += q.y;
    }
    float iv = g_inv[n];
    const float* r = &nf[n * 4];
    float n0 = r[0], n1 = r[1], n2 = r[2], n3 = r[3];
    float sx = n0*sW[2*l]   + n1*sW[64+2*l]   + n2*sW[128+2*l]   + n3*sW[192+2*l];
    float sy = n0*sW[2*l+1] + n1*sW[64+2*l+1] + n2*sW[128+2*l+1] + n3*sW[192+2*l+1];
    float2 o;
    o.x = fmaxf(sx + ax * iv + b[2*l],     0.f);
    o.y = fmaxf(sy + ay * iv + b[2*l+1],   0.f);
    *(float2*)&g_h1[(size_t)n * HD + 2*l] = o;
}

// ================= WMMA GEMM stages (fp16 in, fp32 accum) ===================

// ---- dual: p16 = X@Wn (half2), outf = X@Ws (fp32), no bias ----------------
__global__ void k_wdual(const float* __restrict__ in, const float* __restrict__ Wn,
                        const float* __restrict__ Ws, float* __restrict__ outf) {
    __shared__ __align__(32) __half Xh[128 * HD];
    __shared__ __align__(32) __half WA[HD * HD];
    __shared__ __align__(32) __half WB[HD * HD];
    __shared__ float scr[8][256];
    int tid = threadIdx.x, w = tid >> 5, lane = tid & 31;
    int nbase = blockIdx.x * 128;
    int base = nbase * HD;
    for (int t = tid; t < 128 * HD; t += 256) {
        int gi = base + t;
        Xh[t] = (gi < NN * HD) ? __float2half(in[gi]) : __half(0.f);
    }
    for (int t = tid; t < HD * HD; t += 256) {
        WA[t] = __float2half(Wn[t]);
        WB[t] = __float2half(Ws[t]);
    }
    __syncthreads();
    int r0 = w * 16;
#pragma unroll
    for (int nt = 0; nt < 4; nt++) {
        wm::fragment<wm::accumulator, 16, 16, 16, float> accA, accB;
        wm::fill_fragment(accA, 0.f);
        wm::fill_fragment(accB, 0.f);
#pragma unroll
        for (int kt = 0; kt < 4; kt++) {
            wm::fragment<wm::matrix_a, 16, 16, 16, __half, wm::row_major> a;
            wm::fragment<wm::matrix_b, 16, 16, 16, __half, wm::row_major> bA, bB;
            wm::load_matrix_sync(a, Xh + r0 * HD + kt * 16, HD);
            wm::load_matrix_sync(bA, WA + kt * 16 * HD + nt * 16, HD);
            wm::load_matrix_sync(bB, WB + kt * 16 * HD + nt * 16, HD);
            wm::mma_sync(accA, a, bA, accA);
            wm::mma_sync(accB, a, bB, accB);
        }
        wm::store_matrix_sync(scr[w], accB, 16, wm::mem_row_major);
        __syncwarp();
        for (int t = lane; t < 256; t += 32) {
            int row = t >> 4, col = t & 15;
            int n = nbase + r0 + row;
            if (n < NN) outf[(size_t)n * HD + nt * 16 + col] = scr[w][t];
        }
        __syncwarp();
        wm::store_matrix_sync(scr[w], accA, 16, wm::mem_row_major);
        __syncwarp();
        for (int t = lane; t < 128; t += 32) {
            int row = t >> 3, cp = t & 7;
            int n = nbase + r0 + row;
            if (n < NN)
                g_p16[(size_t)n * 32 + nt * 8 + cp] =
                    __floats2half2_rn(scr[w][row * 16 + 2 * cp], scr[w][row * 16 + 2 * cp + 1]);
        }
        __syncwarp();
    }
}

// ---- fused: hp = relu(h2@Wnp + bnp) in smem, then both role table GEMMs ----
__global__ void k_wfuse(const float* __restrict__ h2in, const float* __restrict__ Wnp,
                        const float* __restrict__ bnp,
                        const float* __restrict__ We1, const float* __restrict__ Wl1,
                        unsigned int* __restrict__ utab_s, unsigned int* __restrict__ utab_d) {
    __shared__ __align__(32) __half Xh[128 * HD];   // phase1 A operand / phase2 scratch
    __shared__ __align__(32) __half Yh[128 * HD];   // hp tile (phase2 A operand)
    __shared__ __align__(32) __half WA[HD * HD];
    __shared__ __align__(32) __half WB[HD * HD];    // phase1 scratch / phase2 Wl weights
    int tid = threadIdx.x, w = tid >> 5, lane = tid & 31;
    int nbase = blockIdx.x * 128;
    int base = nbase * HD;
    for (int t = tid; t < 128 * HD; t += 256) {
        int gi = base + t;
        Xh[t] = (gi < NN * HD) ? __float2half(h2in[gi]) : __half(0.f);
    }
    for (int t = tid; t < HD * HD; t += 256) WA[t] = __float2half(Wnp[t]);
    __syncthreads();

    int r0 = w * 16;
    // ---- phase 1: hp tile into Yh ----
    {
        float* scr1 = (float*)WB;
#pragma unroll
        for (int nt = 0; nt < 4; nt++) {
            wm::fragment<wm::accumulator, 16, 16, 16, float> acc;
            wm::fill_fragment(acc, 0.f);
#pragma unroll
            for (int kt = 0; kt < 4; kt++) {
                wm::fragment<wm::matrix_a, 16, 16, 16, __half, wm::row_major> a;
                wm::fragment<wm::matrix_b, 16, 16, 16, __half, wm::row_major> b;
                wm::load_matrix_sync(a, Xh + r0 * HD + kt * 16, HD);
                wm::load_matrix_sync(b, WA + kt * 16 * HD + nt * 16, HD);
                wm::mma_sync(acc, a, b, acc);
            }
            wm::store_matrix_sync(scr1 + w * 256, acc, 16, wm::mem_row_major);
            __syncwarp();
            for (int t = lane; t < 256; t += 32) {
                int row = t >> 4, col = t & 15;
                float v = scr1[w * 256 + t] + __ldg(&bnp[nt * 16 + col]);
                Yh[(r0 + row) * HD + nt * 16 + col] = __float2half(fmaxf(v, 0.f));
            }
            __syncwarp();
        }
    }
    __syncthreads();

    // ---- phase 2: two roles, tables from Yh ----
    float* scr2 = (float*)Xh;
    for (int role = 0; role < 2; role++) {
        const float* Wa = We1 + role * 64 * HD;
        const float* Wb = Wl1 + role * 64 * HD;
        unsigned int* utab = role ? utab_d : utab_s;
        for (int t = tid; t < HD * HD; t += 256) {
            WA[t] = __float2half(Wa[t]);
            WB[t] = __float2half(Wb[t]);
        }
        __syncthreads();
#pragma unroll
        for (int nt = 0; nt < 4; nt++) {
            wm::fragment<wm::accumulator, 16, 16, 16, float> accA, accB;
            wm::fill_fragment(accA, 0.f);
            wm::fill_fragment(accB, 0.f);
#pragma unroll
            for (int kt = 0; kt < 4; kt++) {
                wm::fragment<wm::matrix_a, 16, 16, 16, __half, wm::row_major> a;
                wm::fragment<wm::matrix_b, 16, 16, 16, __half, wm::row_major> bA, bB;
                wm::load_matrix_sync(a, Yh + r0 * HD + kt * 16, HD);
                wm::load_matrix_sync(bA, WA + kt * 16 * HD + nt * 16, HD);
                wm::load_matrix_sync(bB, WB + kt * 16 * HD + nt * 16, HD);
                wm::mma_sync(accA, a, bA, accA);
                wm::mma_sync(accB, a, bB, accB);
            }
            wm::store_matrix_sync(scr2 + w * 256, accA, 16, wm::mem_row_major);
            __syncwarp();
            for (int t = lane; t < 128; t += 32) {
                int row = t >> 3, cp = t & 7;
                int n = nbase + r0 + row;
                if (n < NN) {
                    __half2 h = __floats2half2_rn(scr2[w * 256 + row * 16 + 2 * cp],
                                                  scr2[w * 256 + row * 16 + 2 * cp + 1]);
                    utab[((size_t)n * 32 + nt * 8 + cp) * 2] = *(unsigned int*)&h;
                }
            }
            __syncwarp();
            wm::store_matrix_sync(scr2 + w * 256, accB, 16, wm::mem_row_major);
            __syncwarp();
            for (int t = lane; t < 128; t += 32) {
                int row = t >> 3, cp = t & 7;
                int n = nbase + r0 + row;
                if (n < NN) {
                    __half2 h = __floats2half2_rn(scr2[w * 256 + row * 16 + 2 * cp],
                                                  scr2[w * 256 + row * 16 + 2 * cp + 1]);
                    utab[((size_t)n * 32 + nt * 8 + cp) * 2 + 1] = *(unsigned int*)&h;
                }
            }
            __syncwarp();
        }
        __syncthreads();
    }
}

// ---------------- SAGE layer 2 combine (MLP=16/8/4 gathers) ------------------
__global__ void k_sage2b(const float* __restrict__ b) {
    int tid = threadIdx.x;
    int n = blockIdx.x * 8 + (tid >> 5);
    int l = tid & 31;
    if (n >= NN) return;
    int beg = g_off[n], end = g_off[n + 1];
    float ax = 0.f, ay = 0.f;
    int j = beg;
    for (; j + 16 <= end; j += 16) {
        int si[16];
#pragma unroll
        for (int t = 0; t < 16; t++) si[t] = g_csr_src[j + t];
        float2 q[16];
#pragma unroll
        for (int t = 0; t < 16; t++) q[t] = __half22float2(g_p16[si[t] * 32 + l]);
        float a0 = 0.f, a1 = 0.f;
#pragma unroll
        for (int t = 0; t < 16; t++) { a0 += q[t].x; a1 += q[t].y; }
        ax += a0; ay += a1;
    }
    for (; j + 8 <= end; j += 8) {
        int s0 = g_csr_src[j],     s1 = g_csr_src[j + 1];
        int s2 = g_csr_src[j + 2], s3 = g_csr_src[j + 3];
        int s4 = g_csr_src[j + 4], s5 = g_csr_src[j + 5];
        int s6 = g_csr_src[j + 6], s7 = g_csr_src[j + 7];
        float2 q0 = __half22float2(g_p16[s0 * 32 + l]);
        float2 q1 = __half22float2(g_p16[s1 * 32 + l]);
        float2 q2 = __half22float2(g_p16[s2 * 32 + l]);
        float2 q3 = __half22float2(g_p16[s3 * 32 + l]);
        float2 q4 = __half22float2(g_p16[s4 * 32 + l]);
        float2 q5 = __half22float2(g_p16[s5 * 32 + l]);
        float2 q6 = __half22float2(g_p16[s6 * 32 + l]);
        float2 q7 = __half22float2(g_p16[s7 * 32 + l]);
        ax += ((q0.x + q1.x) + (q2.x + q3.x)) + ((q4.x + q5.x) + (q6.x + q7.x));
        ay += ((q0.y + q1.y) + (q2.y + q3.y)) + ((q4.y + q5.y) + (q6.y + q7.y));
    }
    for (; j + 4 <= end; j += 4) {
        int s0 = g_csr_src[j],     s1 = g_csr_src[j + 1];
        int s2 = g_csr_src[j + 2], s3 = g_csr_src[j + 3];
        float2 q0 = __half22float2(g_p16[s0 * 32 + l]);
        float2 q1 = __half22float2(g_p16[s1 * 32 + l]);
        float2 q2 = __half22float2(g_p16[s2 * 32 + l]);
        float2 q3 = __half22float2(g_p16[s3 * 32 + l]);
        ax += (q0.x + q1.x) + (q2.x + q3.x);
        ay += (q0.y + q1.y) + (q2.y + q3.y);
    }
    for (; j < end; j++) {
        float2 q = __half22float2(g_p16[g_csr_src[j] * 32 + l]);
        ax += q.x; ay += q.y;
    }
    float iv = g_inv[n];
    float2 t = *(const float2*)&g_h2[(size_t)n * HD + 2 * l];
    float2 o;
    o.x = fmaxf(t.x + ax * iv + b[2 * l],     0.f);
    o.y = fmaxf(t.y + ay * iv + b[2 * l + 1], 0.f);
    *(float2*)&g_h2[(size_t)n * HD + 2 * l] = o;
}

// ------- edge kernel: 8 lanes/edge, 4 edges/warp, 2-deep table pipeline ------
__global__ void __launch_bounds__(256, 2) k_edge(
                       const int* __restrict__ src, const int* __restrict__ dst,
                       const float* __restrict__ ef,
                       const float* __restrict__ We1, const float* __restrict__ be1,
                       const float* __restrict__ We2, const float* __restrict__ be2,
                       const float* __restrict__ Wl1, const float* __restrict__ bl1,
                       const float* __restrict__ Wl2, const float* __restrict__ bl2,
                       float* __restrict__ out) {
    int tid = threadIdx.x;
    int l = tid & 31;
    int li = l & 7;             // lane within 8-lane edge group
    int g = l >> 3;             // which of the 4 edges
    int base = l & 24;          // shfl base for my group
    int warp = (blockIdx.x * blockDim.x + tid) >> 5;
    int nw = (gridDim.x * blockDim.x) >> 5;
    int stepE = 4 * nw;

    // per-lane constants: feats 8*li .. 8*li+7
    __half2 weh[5][4], wlh[5][4];
#pragma unroll
    for (int k = 0; k < 5; k++) {
        float4 a0 = *(const float4*)&We1[(128 + k) * HD + 8 * li];
        float4 a1 = *(const float4*)&We1[(128 + k) * HD + 8 * li + 4];
        float4 b0 = *(const float4*)&Wl1[(128 + k) * HD + 8 * li];
        float4 b1 = *(const float4*)&Wl1[(128 + k) * HD + 8 * li + 4];
        weh[k][0] = __floats2half2_rn(a0.x, a0.y);
        weh[k][1] = __floats2half2_rn(a0.z, a0.w);
        weh[k][2] = __floats2half2_rn(a1.x, a1.y);
        weh[k][3] = __floats2half2_rn(a1.z, a1.w);
        wlh[k][0] = __floats2half2_rn(b0.x, b0.y);
        wlh[k][1] = __floats2half2_rn(b0.z, b0.w);
        wlh[k][2] = __floats2half2_rn(b1.x, b1.y);
        wlh[k][3] = __floats2half2_rn(b1.z, b1.w);
    }
    float4 be1a = *(const float4*)&be1[8 * li];
    float4 be1b = *(const float4*)&be1[8 * li + 4];
    __half2 be1h[4];
    be1h[0] = __floats2half2_rn(be1a.x, be1a.y);
    be1h[1] = __floats2half2_rn(be1a.z, be1a.w);
    be1h[2] = __floats2half2_rn(be1b.x, be1b.y);
    be1h[3] = __floats2half2_rn(be1b.z, be1b.w);
    float4 bl1a = *(const float4*)&bl1[8 * li];
    float4 bl1b = *(const float4*)&bl1[8 * li + 4];
    float4 we2a = *(const float4*)&We2[8 * li];
    float4 we2b = *(const float4*)&We2[8 * li + 4];
    float4 wl2a = *(const float4*)&Wl2[8 * li];
    float4 wl2b = *(const float4*)&Wl2[8 * li + 4];
    float be2v = be2[0], bl2v = bl2[0];

    // ---- pipeline prologue ----
    int e0 = warp * 4 + g;
    int sCur = 0, dCur = 0;
    float efA = 0.f;
    if (e0 < NE) {
        sCur = __ldg(&src[e0]);
        dCur = __ldg(&dst[e0]);
        efA = (li < 5) ? __ldg(&ef[(size_t)e0 * 5 + li]) : 0.f;
    }
    uint4 cs0, cs1, cd0, cd1;
    {
        const uint4* ps = &g_srct[(size_t)sCur * 16];
        const uint4* pd = &g_dstt[(size_t)dCur * 16];
        cs0 = ps[2 * li];  cs1 = ps[2 * li + 1];
        cd0 = pd[2 * li];  cd1 = pd[2 * li + 1];
    }
    int e1 = e0 + stepE;
    int sNxt = 0, dNxt = 0;
    float efB = 0.f;
    if (e1 < NE) {
        sNxt = __ldg(&src[e1]);
        dNxt = __ldg(&dst[e1]);
        efB = (li < 5) ? __ldg(&ef[(size_t)e1 * 5 + li]) : 0.f;
    }

    for (int eb = warp * 4; eb < NE; eb += stepE) {
        int ecur = eb + g;
        // 1) issue next-iteration table gathers (indices already resident)
        uint4 ns0, ns1, nd0, nd1;
        {
            const uint4* ps = &g_srct[(size_t)sNxt * 16];
            const uint4* pd = &g_dstt[(size_t)dNxt * 16];
            ns0 = ps[2 * li];  ns1 = ps[2 * li + 1];
            nd0 = pd[2 * li];  nd1 = pd[2 * li + 1];
        }
        // 2) issue next-next index loads
        int e2 = ecur + 2 * stepE;
        int sNN = 0, dNN = 0;
        float efC = 0.f;
        if (e2 < NE) {
            sNN = __ldg(&src[e2]);
            dNN = __ldg(&dst[e2]);
            efC = (li < 5) ? __ldg(&ef[(size_t)e2 * 5 + li]) : 0.f;
        }

        // 3) compute with current tables (cs*, cd*, efA)
        __half2 efh = __float2half2_rn(efA);
        __half2 tW0 = __hadd2(__hadd2(H2(cs0.x), H2(cd0.x)), be1h[0]);
        __half2 tW1 = __hadd2(__hadd2(H2(cs0.z), H2(cd0.z)), be1h[1]);
        __half2 tW2 = __hadd2(__hadd2(H2(cs1.x), H2(cd1.x)), be1h[2]);
        __half2 tW3 = __hadd2(__hadd2(H2(cs1.z), H2(cd1.z)), be1h[3]);
        __half2 tL0 = __hadd2(H2(cs0.y), H2(cd0.y));
        __half2 tL1 = __hadd2(H2(cs0.w), H2(cd0.w));
        __half2 tL2 = __hadd2(H2(cs1.y), H2(cd1.y));
        __half2 tL3 = __hadd2(H2(cs1.w), H2(cd1.w));

        unsigned int efu = *(unsigned int*)&efh;
        unsigned int eku = __shfl_sync(0xffffffffu, efu, base);
        __half2 ekh = *(__half2*)&eku;
        __half2 cW0 = __hmul2(ekh, weh[0][0]);
        __half2 cW1 = __hmul2(ekh, weh[0][1]);
        __half2 cW2 = __hmul2(ekh, weh[0][2]);
        __half2 cW3 = __hmul2(ekh, weh[0][3]);
        __half2 cL0 = __hmul2(ekh, wlh[0][0]);
        __half2 cL1 = __hmul2(ekh, wlh[0][1]);
        __half2 cL2 = __hmul2(ekh, wlh[0][2]);
        __half2 cL3 = __hmul2(ekh, wlh[0][3]);
#pragma unroll
        for (int k = 1; k < 5; k++) {
            eku = __shfl_sync(0xffffffffu, efu, base + k);
            ekh = *(__half2*)&eku;
            cW0 = __hfma2(ekh, weh[k][0], cW0);
            cW1 = __hfma2(ekh, weh[k][1], cW1);
            cW2 = __hfma2(ekh, weh[k][2], cW2);
            cW3 = __hfma2(ekh, weh[k][3], cW3);
            cL0 = __hfma2(ekh, wlh[k][0], cL0);
            cL1 = __hfma2(ekh, wlh[k][1], cL1);
            cL2 = __hfma2(ekh, wlh[k][2], cL2);
            cL3 = __hfma2(ekh, wlh[k][3], cL3);
        }
        float2 u0 = __half22float2(tW0), w0 = __half22float2(cW0);
        float2 u1 = __half22float2(tW1), w1 = __half22float2(cW1);
        float2 u2 = __half22float2(tW2), w2 = __half22float2(cW2);
        float2 u3 = __half22float2(tW3), w3 = __half22float2(cW3);
        float part = tanh_fast(u0.x + w0.x) * we2a.x + tanh_fast(u0.y + w0.y) * we2a.y
                   + tanh_fast(u1.x + w1.x) * we2a.z + tanh_fast(u1.y + w1.y) * we2a.w
                   + tanh_fast(u2.x + w2.x) * we2b.x + tanh_fast(u2.y + w2.y) * we2b.y
                   + tanh_fast(u3.x + w3.x) * we2b.z + tanh_fast(u3.y + w3.y) * we2b.w;
#pragma unroll
        for (int o = 4; o > 0; o >>= 1) part += __shfl_xor_sync(0xffffffffu, part, o);
        float wgt = 1.f / (1.f + __expf(-(part + be2v)));

        float2 v0 = __half22float2(tL0), x0 = __half22float2(cL0);
        float2 v1 = __half22float2(tL1), x1 = __half22float2(cL1);
        float2 v2 = __half22float2(tL2), x2 = __half22float2(cL2);
        float2 v3 = __half22float2(tL3), x3 = __half22float2(cL3);
        float o0 = fmaxf(fmaf(wgt, v0.x + x0.x, bl1a.x), 0.f);
        float o1 = fmaxf(fmaf(wgt, v0.y + x0.y, bl1a.y), 0.f);
        float o2 = fmaxf(fmaf(wgt, v1.x + x1.x, bl1a.z), 0.f);
        float o3 = fmaxf(fmaf(wgt, v1.y + x1.y, bl1a.w), 0.f);
        float o4 = fmaxf(fmaf(wgt, v2.x + x2.x, bl1b.x), 0.f);
        float o5 = fmaxf(fmaf(wgt, v2.y + x2.y, bl1b.y), 0.f);
        float o6 = fmaxf(fmaf(wgt, v3.x + x3.x, bl1b.z), 0.f);
        float o7 = fmaxf(fmaf(wgt, v3.y + x3.y, bl1b.w), 0.f);
        float p2 = (o0 * wl2a.x + o1 * wl2a.y) + (o2 * wl2a.z + o3 * wl2a.w)
                 + (o4 * wl2b.x + o5 * wl2b.y) + (o6 * wl2b.z + o7 * wl2b.w);
#pragma unroll
        for (int o = 4; o > 0; o >>= 1) p2 += __shfl_xor_sync(0xffffffffu, p2, o);
        if (li == 0) out[ecur] = p2 + bl2v;

        // 4) rotate pipeline
        cs0 = ns0; cs1 = ns1; cd0 = nd0; cd1 = nd1;
        efA = efB; efB = efC;
        sNxt = sNN; dNxt = dNN;
    }
}

// ---------------- launch -----------------------------------------------------
extern "C" void kernel_launch(void* const* d_in, const int* in_sizes, int n_in,
                              void* d_out, int out_size) {
    const float* node_feat = (const float*)d_in[0];
    const float* edge_feat = (const float*)d_in[1];
    const int*   src       = (const int*)d_in[2];
    const int*   dst       = (const int*)d_in[3];
    const float* W1s = (const float*)d_in[4];
    const float* W1n = (const float*)d_in[5];
    const float* b1  = (const float*)d_in[6];
    const float* W2s = (const float*)d_in[7];
    const float* W2n = (const float*)d_in[8];
    const float* b2  = (const float*)d_in[9];
    const float* Wnp = (const float*)d_in[10];
    const float* bnp = (const float*)d_in[11];
    const float* We1 = (const float*)d_in[12];
    const float* be1 = (const float*)d_in[13];
    const float* We2 = (const float*)d_in[14];
    const float* be2 = (const float*)d_in[15];
    const float* Wl1 = (const float*)d_in[16];
    const float* bl1 = (const float*)d_in[17];
    const float* Wl2 = (const float*)d_in[18];
    const float* bl2 = (const float*)d_in[19];
    float* out = (float*)d_out;

    float *ph1, *ph2;
    void *pst, *pdt, *pdc;
    cudaGetSymbolAddress((void**)&ph1, g_h1);
    cudaGetSymbolAddress((void**)&ph2, g_h2);
    cudaGetSymbolAddress(&pst, g_srct);
    cudaGetSymbolAddress(&pdt, g_dstt);
    cudaGetSymbolAddress(&pdc, g_dc);

    int nb   = (NN + 1023) / 1024;
    int nblk = (NN + 7) / 8;          // warp-per-node kernels
    int wblk = (NN + 127) / 128;      // WMMA kernels (128 nodes/block)

    cudaMemsetAsync(pdc, 0, NN * sizeof(int));
    // fused: p1 projection + degree histogram (independent work, one launch)
    k_dp<<<PROJ_B + DEG_B, 256>>>(dst, node_feat, W1n);
    k_scan1<<<nb, 1024>>>();
    k_scan2<<<1, 128>>>(nb);
    k_scan3<<<(NN + 255) / 256, 256>>>();
    k_scatter<<<(NE + 255) / 256, 256>>>(src, dst);

    // Layer 1
    k_sage1<<<nblk, 256>>>(node_feat, W1s, b1);

    // Layer 2: p2 = h1@W2n (half2) AND h1@W2s (fp32) via WMMA, then combine
    k_wdual<<<wblk, 256>>>(ph1, W2n, W2s, ph2);
    k_sage2b<<<nblk, 256>>>(b2);

    // fused: hp = relu(h2@Wnp+bnp) in smem, then both role tables
    k_wfuse<<<wblk, 256>>>(ph2, Wnp, bnp, We1, Wl1,
                           (unsigned int*)pst, (unsigned int*)pdt);

    // persistent fused edge stage: 8 lanes/edge, 4 edges/warp, 2-deep pipeline
    k_edge<<<592, 256>>>(src, dst, edge_feat,
                         We1, be1, We2, be2, Wl1, bl1, Wl2, bl2, out);
}

// round 17
// speedup vs baseline: 1.0206x; 1.0057x over previous
#include <cuda_runtime.h>
#include <cuda_fp16.h>
#include <mma.h>

#define NN 100000
#define NE 1600000
#define HD 64
#define NB_SCAN ((NN + 1023) / 1024)

namespace wm = nvcuda::wmma;

// ---------------- scratch (device globals; no allocation allowed) ----------
__device__ int   g_dc[NN];           // deg, then reused as scatter cursor
__device__ float g_inv[NN];
__device__ int   g_off[NN + 1];
__device__ int   g_bsum[128];
__device__ int   g_csr_src[NE];
__device__ __half2 g_p16[NN * 32];   // projected neighbor features (half2 pairs)
__device__ float g_h1[NN * HD];      // h1
__device__ float g_h2[NN * HD];      // h2
// per-node tables: 16 x uint4 per node; as uint2[32]:
// idx j = {We-pair(feats 2j,2j+1) , Wl-pair} interleaved
__device__ uint4 g_srct[NN * 16];
__device__ uint4 g_dstt[NN * 16];

__device__ __forceinline__ float tanh_fast(float x) {
    float y;
    asm("tanh.approx.f32 %0, %1;" : "=f"(y) : "f"(x));
    return y;
}
#define H2(u) (*(__half2*)&(u))

// ---------------- fused: degree histogram + p1 projection -------------------
#define PROJ_B ((NN * 32 + 255) / 256)
#define DEG_B  ((NE + 255) / 256)
__global__ void k_dp(const int* __restrict__ dst, const float* __restrict__ nf,
                     const float* __restrict__ W) {
    int bid = blockIdx.x;
    int tid = threadIdx.x;
    if (bid < PROJ_B) {
        __shared__ float sW[4 * HD];
        sW[tid] = W[tid];
        __syncthreads();
        int idx = bid * 256 + tid;
        if (idx >= NN * 32) return;
        int n = idx >> 5, j = idx & 31;
        const float* r = &nf[n * 4];
        float r0 = r[0], r1 = r[1], r2 = r[2], r3 = r[3];
        float v0 = r0 * sW[2*j]   + r1 * sW[64 + 2*j]   + r2 * sW[128 + 2*j]   + r3 * sW[192 + 2*j];
        float v1 = r0 * sW[2*j+1] + r1 * sW[64 + 2*j+1] + r2 * sW[128 + 2*j+1] + r3 * sW[192 + 2*j+1];
        g_p16[idx] = __floats2half2_rn(v0, v1);
    } else {
        int e = (bid - PROJ_B) * 256 + tid;
        if (e < NE) atomicAdd(&g_dc[dst[e]], 1);
    }
}

// ---------------- scan stage 1: per-1024-block exclusive scan ----------------
__global__ void k_scan1() {
    __shared__ int sh[1024];
    int tid = threadIdx.x;
    int i = blockIdx.x * 1024 + tid;
    int v = (i < NN) ? g_dc[i] : 0;
    sh[tid] = v;
    __syncthreads();
    for (int o = 1; o < 1024; o <<= 1) {
        int t = (tid >= o) ? sh[tid - o] : 0;
        __syncthreads();
        sh[tid] += t;
        __syncthreads();
    }
    if (i < NN) g_off[i] = sh[tid] - v;      // exclusive within block
    if (tid == 1023) g_bsum[blockIdx.x] = sh[1023];
}

// ---- scan stage 2 (fused): every block redundantly scans g_bsum, then
//      finalizes offsets, writes inv, re-seeds g_dc as the scatter cursor ----
__global__ void k_scan3() {
    __shared__ int sb[128];
    int tid = threadIdx.x;
    // load + exclusive-scan the (<=98) block sums in shared (redundant per block)
    int v = (tid < 128) ? ((tid < NB_SCAN) ? g_bsum[tid] : 0) : 0;
    if (tid < 128) sb[tid] = v;
    __syncthreads();
    for (int o = 1; o < 128; o <<= 1) {
        int t = 0;
        if (tid < 128 && tid >= o) t = sb[tid - o];
        __syncthreads();
        if (tid < 128) sb[tid] += t;
        __syncthreads();
    }
    // sb now inclusive; exclusive prefix for block k is sb[k] - bsum[k]... easier:
    int i = blockIdx.x * 256 + tid;
    if (i < NN) {
        int blk = i >> 10;
        int pre = sb[blk] - g_bsum[blk];     // exclusive prefix of block blk
        int off = g_off[i] + pre;
        int d = g_dc[i];
        g_off[i] = off;
        g_dc[i] = off;                       // scatter cursor
        g_inv[i] = 1.0f / (float)(d > 0 ? d : 1);
    }
    if (i == 0) g_off[NN] = NE;              // total edge count is a constant
}

// ---------------- CSR scatter (cursor in g_dc) -------------------------------
__global__ void k_scatter(const int* __restrict__ src, const int* __restrict__ dst) {
    int e = blockIdx.x * blockDim.x + threadIdx.x;
    if (e < NE) {
        int pos = atomicAdd(&g_dc[dst[e]], 1);
        g_csr_src[pos] = src[e];
    }
}

// ---------------- SAGE layer 1 (MLP=16/8/4 gathers) --------------------------
__global__ void k_sage1(const float* __restrict__ nf, const float* __restrict__ Ws,
                        const float* __restrict__ b) {
    __shared__ float sW[4 * HD];
    int tid = threadIdx.x;
    sW[tid] = Ws[tid];
    __syncthreads();
    int n = blockIdx.x * 8 + (tid >> 5);
    int l = tid & 31;
    if (n >= NN) return;
    int beg = g_off[n], end = g_off[n + 1];
    float ax = 0.f, ay = 0.f;
    int j = beg;
    for (; j + 16 <= end; j += 16) {
        int si[16];
#pragma unroll
        for (int t = 0; t < 16; t++) si[t] = g_csr_src[j + t];
        float2 q[16];
#pragma unroll
        for (int t = 0; t < 16; t++) q[t] = __half22float2(g_p16[si[t] * 32 + l]);
        float a0 = 0.f, a1 = 0.f;
#pragma unroll
        for (int t = 0; t < 16; t++) { a0 += q[t].x; a1 += q[t].y; }
        ax += a0; ay += a1;
    }
    for (; j + 8 <= end; j += 8) {
        int s0 = g_csr_src[j],     s1 = g_csr_src[j + 1];
        int s2 = g_csr_src[j + 2], s3 = g_csr_src[j + 3];
        int s4 = g_csr_src[j + 4], s5 = g_csr_src[j + 5];
        int s6 = g_csr_src[j + 6], s7 = g_csr_src[j + 7];
        float2 q0 = __half22float2(g_p16[s0 * 32 + l]);
        float2 q1 = __half22float2(g_p16[s1 * 32 + l]);
        float2 q2 = __half22float2(g_p16[s2 * 32 + l]);
        float2 q3 = __half22float2(g_p16[s3 * 32 + l]);
        float2 q4 = __half22float2(g_p16[s4 * 32 + l]);
        float2 q5 = __half22float2(g_p16[s5 * 32 + l]);
        float2 q6 = __half22float2(g_p16[s6 * 32 + l]);
        float2 q7 = __half22float2(g_p16[s7 * 32 + l]);
        ax += ((q0.x + q1.x) + (q2.x + q3.x)) + ((q4.x + q5.x) + (q6.x + q7.x));
        ay += ((q0.y + q1.y) + (q2.y + q3.y)) + ((q4.y + q5.y) + (q6.y + q7.y));
    }
    for (; j + 4 <= end; j += 4) {
        int s0 = g_csr_src[j],     s1 = g_csr_src[j + 1];
        int s2 = g_csr_src[j + 2], s3 = g_csr_src[j + 3];
        float2 q0 = __half22float2(g_p16[s0 * 32 + l]);
        float2 q1 = __half22float2(g_p16[s1 * 32 + l]);
        float2 q2 = __half22float2(g_p16[s2 * 32 + l]);
        float2 q3 = __half22float2(g_p16[s3 * 32 + l]);
        ax += (q0.x + q1.x) + (q2.x + q3.x);
        ay += (q0.y + q1.y) + (q2.y + q3.y);
    }
    for (; j < end; j++) {
        float2 q = __half22float2(g_p16[g_csr_src[j] * 32 + l]);
        ax += q.x; ay += q.y;
    }
    float iv = g_inv[n];
    const float* r = &nf[n * 4];
    float n0 = r[0], n1 = r[1], n2 = r[2], n3 = r[3];
    float sx = n0*sW[2*l]   + n1*sW[64+2*l]   + n2*sW[128+2*l]   + n3*sW[192+2*l];
    float sy = n0*sW[2*l+1] + n1*sW[64+2*l+1] + n2*sW[128+2*l+1] + n3*sW[192+2*l+1];
    float2 o;
    o.x = fmaxf(sx + ax * iv + b[2*l],     0.f);
    o.y = fmaxf(sy + ay * iv + b[2*l+1],   0.f);
    *(float2*)&g_h1[(size_t)n * HD + 2*l] = o;
}

// ================= WMMA GEMM stages (fp16 in, fp32 accum) ===================

// ---- dual: p16 = X@Wn (half2), outf = X@Ws (fp32), no bias ----------------
__global__ void k_wdual(const float* __restrict__ in, const float* __restrict__ Wn,
                        const float* __restrict__ Ws, float* __restrict__ outf) {
    __shared__ __align__(32) __half Xh[128 * HD];
    __shared__ __align__(32) __half WA[HD * HD];
    __shared__ __align__(32) __half WB[HD * HD];
    __shared__ float scr[8][256];
    int tid = threadIdx.x, w = tid >> 5, lane = tid & 31;
    int nbase = blockIdx.x * 128;
    int base = nbase * HD;
    for (int t = tid; t < 128 * HD; t += 256) {
        int gi = base + t;
        Xh[t] = (gi < NN * HD) ? __float2half(in[gi]) : __half(0.f);
    }
    for (int t = tid; t < HD * HD; t += 256) {
        WA[t] = __float2half(Wn[t]);
        WB[t] = __float2half(Ws[t]);
    }
    __syncthreads();
    int r0 = w * 16;
#pragma unroll
    for (int nt = 0; nt < 4; nt++) {
        wm::fragment<wm::accumulator, 16, 16, 16, float> accA, accB;
        wm::fill_fragment(accA, 0.f);
        wm::fill_fragment(accB, 0.f);
#pragma unroll
        for (int kt = 0; kt < 4; kt++) {
            wm::fragment<wm::matrix_a, 16, 16, 16, __half, wm::row_major> a;
            wm::fragment<wm::matrix_b, 16, 16, 16, __half, wm::row_major> bA, bB;
            wm::load_matrix_sync(a, Xh + r0 * HD + kt * 16, HD);
            wm::load_matrix_sync(bA, WA + kt * 16 * HD + nt * 16, HD);
            wm::load_matrix_sync(bB, WB + kt * 16 * HD + nt * 16, HD);
            wm::mma_sync(accA, a, bA, accA);
            wm::mma_sync(accB, a, bB, accB);
        }
        wm::store_matrix_sync(scr[w], accB, 16, wm::mem_row_major);
        __syncwarp();
        for (int t = lane; t < 256; t += 32) {
            int row = t >> 4, col = t & 15;
            int n = nbase + r0 + row;
            if (n < NN) outf[(size_t)n * HD + nt * 16 + col] = scr[w][t];
        }
        __syncwarp();
        wm::store_matrix_sync(scr[w], accA, 16, wm::mem_row_major);
        __syncwarp();
        for (int t = lane; t < 128; t += 32) {
            int row = t >> 3, cp = t & 7;
            int n = nbase + r0 + row;
            if (n < NN)
                g_p16[(size_t)n * 32 + nt * 8 + cp] =
                    __floats2half2_rn(scr[w][row * 16 + 2 * cp], scr[w][row * 16 + 2 * cp + 1]);
        }
        __syncwarp();
    }
}

// ---- fused: hp = relu(h2@Wnp + bnp) in smem, then both role table GEMMs ----
__global__ void k_wfuse(const float* __restrict__ h2in, const float* __restrict__ Wnp,
                        const float* __restrict__ bnp,
                        const float* __restrict__ We1, const float* __restrict__ Wl1,
                        unsigned int* __restrict__ utab_s, unsigned int* __restrict__ utab_d) {
    __shared__ __align__(32) __half Xh[128 * HD];   // phase1 A operand / phase2 scratch
    __shared__ __align__(32) __half Yh[128 * HD];   // hp tile (phase2 A operand)
    __shared__ __align__(32) __half WA[HD * HD];
    __shared__ __align__(32) __half WB[HD * HD];    // phase1 scratch / phase2 Wl weights
    int tid = threadIdx.x, w = tid >> 5, lane = tid & 31;
    int nbase = blockIdx.x * 128;
    int base = nbase * HD;
    for (int t = tid; t < 128 * HD; t += 256) {
        int gi = base + t;
        Xh[t] = (gi < NN * HD) ? __float2half(h2in[gi]) : __half(0.f);
    }
    for (int t = tid; t < HD * HD; t += 256) WA[t] = __float2half(Wnp[t]);
    __syncthreads();

    int r0 = w * 16;
    // ---- phase 1: hp tile into Yh ----
    {
        float* scr1 = (float*)WB;
#pragma unroll
        for (int nt = 0; nt < 4; nt++) {
            wm::fragment<wm::accumulator, 16, 16, 16, float> acc;
            wm::fill_fragment(acc, 0.f);
#pragma unroll
            for (int kt = 0; kt < 4; kt++) {
                wm::fragment<wm::matrix_a, 16, 16, 16, __half, wm::row_major> a;
                wm::fragment<wm::matrix_b, 16, 16, 16, __half, wm::row_major> b;
                wm::load_matrix_sync(a, Xh + r0 * HD + kt * 16, HD);
                wm::load_matrix_sync(b, WA + kt * 16 * HD + nt * 16, HD);
                wm::mma_sync(acc, a, b, acc);
            }
            wm::store_matrix_sync(scr1 + w * 256, acc, 16, wm::mem_row_major);
            __syncwarp();
            for (int t = lane; t < 256; t += 32) {
                int row = t >> 4, col = t & 15;
                float v = scr1[w * 256 + t] + __ldg(&bnp[nt * 16 + col]);
                Yh[(r0 + row) * HD + nt * 16 + col] = __float2half(fmaxf(v, 0.f));
            }
            __syncwarp();
        }
    }
    __syncthreads();

    // ---- phase 2: two roles, tables from Yh ----
    float* scr2 = (float*)Xh;
    for (int role = 0; role < 2; role++) {
        const float* Wa = We1 + role * 64 * HD;
        const float* Wb = Wl1 + role * 64 * HD;
        unsigned int* utab = role ? utab_d : utab_s;
        for (int t = tid; t < HD * HD; t += 256) {
            WA[t] = __float2half(Wa[t]);
            WB[t] = __float2half(Wb[t]);
        }
        __syncthreads();
#pragma unroll
        for (int nt = 0; nt < 4; nt++) {
            wm::fragment<wm::accumulator, 16, 16, 16, float> accA, accB;
            wm::fill_fragment(accA, 0.f);
            wm::fill_fragment(accB, 0.f);
#pragma unroll
            for (int kt = 0; kt < 4; kt++) {
                wm::fragment<wm::matrix_a, 16, 16, 16, __half, wm::row_major> a;
                wm::fragment<wm::matrix_b, 16, 16, 16, __half, wm::row_major> bA, bB;
                wm::load_matrix_sync(a, Yh + r0 * HD + kt * 16, HD);
                wm::load_matrix_sync(bA, WA + kt * 16 * HD + nt * 16, HD);
                wm::load_matrix_sync(bB, WB + kt * 16 * HD + nt * 16, HD);
                wm::mma_sync(accA, a, bA, accA);
                wm::mma_sync(accB, a, bB, accB);
            }
            wm::store_matrix_sync(scr2 + w * 256, accA, 16, wm::mem_row_major);
            __syncwarp();
            for (int t = lane; t < 128; t += 32) {
                int row = t >> 3, cp = t & 7;
                int n = nbase + r0 + row;
                if (n < NN) {
                    __half2 h = __floats2half2_rn(scr2[w * 256 + row * 16 + 2 * cp],
                                                  scr2[w * 256 + row * 16 + 2 * cp + 1]);
                    utab[((size_t)n * 32 + nt * 8 + cp) * 2] = *(unsigned int*)&h;
                }
            }
            __syncwarp();
            wm::store_matrix_sync(scr2 + w * 256, accB, 16, wm::mem_row_major);
            __syncwarp();
            for (int t = lane; t < 128; t += 32) {
                int row = t >> 3, cp = t & 7;
                int n = nbase + r0 + row;
                if (n < NN) {
                    __half2 h = __floats2half2_rn(scr2[w * 256 + row * 16 + 2 * cp],
                                                  scr2[w * 256 + row * 16 + 2 * cp + 1]);
                    utab[((size_t)n * 32 + nt * 8 + cp) * 2 + 1] = *(unsigned int*)&h;
                }
            }
            __syncwarp();
        }
        __syncthreads();
    }
}

// ---------------- SAGE layer 2 combine (MLP=16/8/4 gathers) ------------------
__global__ void k_sage2b(const float* __restrict__ b) {
    int tid = threadIdx.x;
    int n = blockIdx.x * 8 + (tid >> 5);
    int l = tid & 31;
    if (n >= NN) return;
    int beg = g_off[n], end = g_off[n + 1];
    float ax = 0.f, ay = 0.f;
    int j = beg;
    for (; j + 16 <= end; j += 16) {
        int si[16];
#pragma unroll
        for (int t = 0; t < 16; t++) si[t] = g_csr_src[j + t];
        float2 q[16];
#pragma unroll
        for (int t = 0; t < 16; t++) q[t] = __half22float2(g_p16[si[t] * 32 + l]);
        float a0 = 0.f, a1 = 0.f;
#pragma unroll
        for (int t = 0; t < 16; t++) { a0 += q[t].x; a1 += q[t].y; }
        ax += a0; ay += a1;
    }
    for (; j + 8 <= end; j += 8) {
        int s0 = g_csr_src[j],     s1 = g_csr_src[j + 1];
        int s2 = g_csr_src[j + 2], s3 = g_csr_src[j + 3];
        int s4 = g_csr_src[j + 4], s5 = g_csr_src[j + 5];
        int s6 = g_csr_src[j + 6], s7 = g_csr_src[j + 7];
        float2 q0 = __half22float2(g_p16[s0 * 32 + l]);
        float2 q1 = __half22float2(g_p16[s1 * 32 + l]);
        float2 q2 = __half22float2(g_p16[s2 * 32 + l]);
        float2 q3 = __half22float2(g_p16[s3 * 32 + l]);
        float2 q4 = __half22float2(g_p16[s4 * 32 + l]);
        float2 q5 = __half22float2(g_p16[s5 * 32 + l]);
        float2 q6 = __half22float2(g_p16[s6 * 32 + l]);
        float2 q7 = __half22float2(g_p16[s7 * 32 + l]);
        ax += ((q0.x + q1.x) + (q2.x + q3.x)) + ((q4.x + q5.x) + (q6.x + q7.x));
        ay += ((q0.y + q1.y) + (q2.y + q3.y)) + ((q4.y + q5.y) + (q6.y + q7.y));
    }
    for (; j + 4 <= end; j += 4) {
        int s0 = g_csr_src[j],     s1 = g_csr_src[j + 1];
        int s2 = g_csr_src[j + 2], s3 = g_csr_src[j + 3];
        float2 q0 = __half22float2(g_p16[s0 * 32 + l]);
        float2 q1 = __half22float2(g_p16[s1 * 32 + l]);
        float2 q2 = __half22float2(g_p16[s2 * 32 + l]);
        float2 q3 = __half22float2(g_p16[s3 * 32 + l]);
        ax += (q0.x + q1.x) + (q2.x + q3.x);
        ay += (q0.y + q1.y) + (q2.y + q3.y);
    }
    for (; j < end; j++) {
        float2 q = __half22float2(g_p16[g_csr_src[j] * 32 + l]);
        ax += q.x; ay += q.y;
    }
    float iv = g_inv[n];
    float2 t = *(const float2*)&g_h2[(size_t)n * HD + 2 * l];
    float2 o;
    o.x = fmaxf(t.x + ax * iv + b[2 * l],     0.f);
    o.y = fmaxf(t.y + ay * iv + b[2 * l + 1], 0.f);
    *(float2*)&g_h2[(size_t)n * HD + 2 * l] = o;
}

// ------- edge kernel: 8 lanes/edge, 4 edges/warp, 2-deep table pipeline ------
__global__ void __launch_bounds__(256, 2) k_edge(
                       const int* __restrict__ src, const int* __restrict__ dst,
                       const float* __restrict__ ef,
                       const float* __restrict__ We1, const float* __restrict__ be1,
                       const float* __restrict__ We2, const float* __restrict__ be2,
                       const float* __restrict__ Wl1, const float* __restrict__ bl1,
                       const float* __restrict__ Wl2, const float* __restrict__ bl2,
                       float* __restrict__ out) {
    int tid = threadIdx.x;
    int l = tid & 31;
    int li = l & 7;             // lane within 8-lane edge group
    int g = l >> 3;             // which of the 4 edges
    int base = l & 24;          // shfl base for my group
    int warp = (blockIdx.x * blockDim.x + tid) >> 5;
    int nw = (gridDim.x * blockDim.x) >> 5;
    int stepE = 4 * nw;

    // per-lane constants: feats 8*li .. 8*li+7
    __half2 weh[5][4], wlh[5][4];
#pragma unroll
    for (int k = 0; k < 5; k++) {
        float4 a0 = *(const float4*)&We1[(128 + k) * HD + 8 * li];
        float4 a1 = *(const float4*)&We1[(128 + k) * HD + 8 * li + 4];
        float4 b0 = *(const float4*)&Wl1[(128 + k) * HD + 8 * li];
        float4 b1 = *(const float4*)&Wl1[(128 + k) * HD + 8 * li + 4];
        weh[k][0] = __floats2half2_rn(a0.x, a0.y);
        weh[k][1] = __floats2half2_rn(a0.z, a0.w);
        weh[k][2] = __floats2half2_rn(a1.x, a1.y);
        weh[k][3] = __floats2half2_rn(a1.z, a1.w);
        wlh[k][0] = __floats2half2_rn(b0.x, b0.y);
        wlh[k][1] = __floats2half2_rn(b0.z, b0.w);
        wlh[k][2] = __floats2half2_rn(b1.x, b1.y);
        wlh[k][3] = __floats2half2_rn(b1.z, b1.w);
    }
    float4 be1a = *(const float4*)&be1[8 * li];
    float4 be1b = *(const float4*)&be1[8 * li + 4];
    __half2 be1h[4];
    be1h[0] = __floats2half2_rn(be1a.x, be1a.y);
    be1h[1] = __floats2half2_rn(be1a.z, be1a.w);
    be1h[2] = __floats2half2_rn(be1b.x, be1b.y);
    be1h[3] = __floats2half2_rn(be1b.z, be1b.w);
    float4 bl1a = *(const float4*)&bl1[8 * li];
    float4 bl1b = *(const float4*)&bl1[8 * li + 4];
    float4 we2a = *(const float4*)&We2[8 * li];
    float4 we2b = *(const float4*)&We2[8 * li + 4];
    float4 wl2a = *(const float4*)&Wl2[8 * li];
    float4 wl2b = *(const float4*)&Wl2[8 * li + 4];
    float be2v = be2[0], bl2v = bl2[0];

    // ---- pipeline prologue ----
    int e0 = warp * 4 + g;
    int sCur = 0, dCur = 0;
    float efA = 0.f;
    if (e0 < NE) {
        sCur = __ldg(&src[e0]);
        dCur = __ldg(&dst[e0]);
        efA = (li < 5) ? __ldg(&ef[(size_t)e0 * 5 + li]) : 0.f;
    }
    uint4 cs0, cs1, cd0, cd1;
    {
        const uint4* ps = &g_srct[(size_t)sCur * 16];
        const uint4* pd = &g_dstt[(size_t)dCur * 16];
        cs0 = ps[2 * li];  cs1 = ps[2 * li + 1];
        cd0 = pd[2 * li];  cd1 = pd[2 * li + 1];
    }
    int e1 = e0 + stepE;
    int sNxt = 0, dNxt = 0;
    float efB = 0.f;
    if (e1 < NE) {
        sNxt = __ldg(&src[e1]);
        dNxt = __ldg(&dst[e1]);
        efB = (li < 5) ? __ldg(&ef[(size_t)e1 * 5 + li]) : 0.f;
    }

    for (int eb = warp * 4; eb < NE; eb += stepE) {
        int ecur = eb + g;
        // 1) issue next-iteration table gathers (indices already resident)
        uint4 ns0, ns1, nd0, nd1;
        {
            const uint4* ps = &g_srct[(size_t)sNxt * 16];
            const uint4* pd = &g_dstt[(size_t)dNxt * 16];
            ns0 = ps[2 * li];  ns1 = ps[2 * li + 1];
            nd0 = pd[2 * li];  nd1 = pd[2 * li + 1];
        }
        // 2) issue next-next index loads
        int e2 = ecur + 2 * stepE;
        int sNN = 0, dNN = 0;
        float efC = 0.f;
        if (e2 < NE) {
            sNN = __ldg(&src[e2]);
            dNN = __ldg(&dst[e2]);
            efC = (li < 5) ? __ldg(&ef[(size_t)e2 * 5 + li]) : 0.f;
        }

        // 3) compute with current tables (cs*, cd*, efA)
        __half2 efh = __float2half2_rn(efA);
        __half2 tW0 = __hadd2(__hadd2(H2(cs0.x), H2(cd0.x)), be1h[0]);
        __half2 tW1 = __hadd2(__hadd2(H2(cs0.z), H2(cd0.z)), be1h[1]);
        __half2 tW2 = __hadd2(__hadd2(H2(cs1.x), H2(cd1.x)), be1h[2]);
        __half2 tW3 = __hadd2(__hadd2(H2(cs1.z), H2(cd1.z)), be1h[3]);
        __half2 tL0 = __hadd2(H2(cs0.y), H2(cd0.y));
        __half2 tL1 = __hadd2(H2(cs0.w), H2(cd0.w));
        __half2 tL2 = __hadd2(H2(cs1.y), H2(cd1.y));
        __half2 tL3 = __hadd2(H2(cs1.w), H2(cd1.w));

        unsigned int efu = *(unsigned int*)&efh;
        unsigned int eku = __shfl_sync(0xffffffffu, efu, base);
        __half2 ekh = *(__half2*)&eku;
        __half2 cW0 = __hmul2(ekh, weh[0][0]);
        __half2 cW1 = __hmul2(ekh, weh[0][1]);
        __half2 cW2 = __hmul2(ekh, weh[0][2]);
        __half2 cW3 = __hmul2(ekh, weh[0][3]);
        __half2 cL0 = __hmul2(ekh, wlh[0][0]);
        __half2 cL1 = __hmul2(ekh, wlh[0][1]);
        __half2 cL2 = __hmul2(ekh, wlh[0][2]);
        __half2 cL3 = __hmul2(ekh, wlh[0][3]);
#pragma unroll
        for (int k = 1; k < 5; k++) {
            eku = __shfl_sync(0xffffffffu, efu, base + k);
            ekh = *(__half2*)&eku;
            cW0 = __hfma2(ekh, weh[k][0], cW0);
            cW1 = __hfma2(ekh, weh[k][1], cW1);
            cW2 = __hfma2(ekh, weh[k][2], cW2);
            cW3 = __hfma2(ekh, weh[k][3], cW3);
            cL0 = __hfma2(ekh, wlh[k][0], cL0);
            cL1 = __hfma2(ekh, wlh[k][1], cL1);
            cL2 = __hfma2(ekh, wlh[k][2], cL2);
            cL3 = __hfma2(ekh, wlh[k][3], cL3);
        }
        float2 u0 = __half22float2(tW0), w0 = __half22float2(cW0);
        float2 u1 = __half22float2(tW1), w1 = __half22float2(cW1);
        float2 u2 = __half22float2(tW2), w2 = __half22float2(cW2);
        float2 u3 = __half22float2(tW3), w3 = __half22float2(cW3);
        float part = tanh_fast(u0.x + w0.x) * we2a.x + tanh_fast(u0.y + w0.y) * we2a.y
                   + tanh_fast(u1.x + w1.x) * we2a.z + tanh_fast(u1.y + w1.y) * we2a.w
                   + tanh_fast(u2.x + w2.x) * we2b.x + tanh_fast(u2.y + w2.y) * we2b.y
                   + tanh_fast(u3.x + w3.x) * we2b.z + tanh_fast(u3.y + w3.y) * we2b.w;
#pragma unroll
        for (int o = 4; o > 0; o >>= 1) part += __shfl_xor_sync(0xffffffffu, part, o);
        float wgt = 1.f / (1.f + __expf(-(part + be2v)));

        float2 v0 = __half22float2(tL0), x0 = __half22float2(cL0);
        float2 v1 = __half22float2(tL1), x1 = __half22float2(cL1);
        float2 v2 = __half22float2(tL2), x2 = __half22float2(cL2);
        float2 v3 = __half22float2(tL3), x3 = __half22float2(cL3);
        float o0 = fmaxf(fmaf(wgt, v0.x + x0.x, bl1a.x), 0.f);
        float o1 = fmaxf(fmaf(wgt, v0.y + x0.y, bl1a.y), 0.f);
        float o2 = fmaxf(fmaf(wgt, v1.x + x1.x, bl1a.z), 0.f);
        float o3 = fmaxf(fmaf(wgt, v1.y + x1.y, bl1a.w), 0.f);
        float o4 = fmaxf(fmaf(wgt, v2.x + x2.x, bl1b.x), 0.f);
        float o5 = fmaxf(fmaf(wgt, v2.y + x2.y, bl1b.y), 0.f);
        float o6 = fmaxf(fmaf(wgt, v3.x + x3.x, bl1b.z), 0.f);
        float o7 = fmaxf(fmaf(wgt, v3.y + x3.y, bl1b.w), 0.f);
        float p2 = (o0 * wl2a.x + o1 * wl2a.y) + (o2 * wl2a.z + o3 * wl2a.w)
                 + (o4 * wl2b.x + o5 * wl2b.y) + (o6 * wl2b.z + o7 * wl2b.w);
#pragma unroll
        for (int o = 4; o > 0; o >>= 1) p2 += __shfl_xor_sync(0xffffffffu, p2, o);
        if (li == 0) out[ecur] = p2 + bl2v;

        // 4) rotate pipeline
        cs0 = ns0; cs1 = ns1; cd0 = nd0; cd1 = nd1;
        efA = efB; efB = efC;
        sNxt = sNN; dNxt = dNN;
    }
}

// ---------------- launch -----------------------------------------------------
extern "C" void kernel_launch(void* const* d_in, const int* in_sizes, int n_in,
                              void* d_out, int out_size) {
    const float* node_feat = (const float*)d_in[0];
    const float* edge_feat = (const float*)d_in[1];
    const int*   src       = (const int*)d_in[2];
    const int*   dst       = (const int*)d_in[3];
    const float* W1s = (const float*)d_in[4];
    const float* W1n = (const float*)d_in[5];
    const float* b1  = (const float*)d_in[6];
    const float* W2s = (const float*)d_in[7];
    const float* W2n = (const float*)d_in[8];
    const float* b2  = (const float*)d_in[9];
    const float* Wnp = (const float*)d_in[10];
    const float* bnp = (const float*)d_in[11];
    const float* We1 = (const float*)d_in[12];
    const float* be1 = (const float*)d_in[13];
    const float* We2 = (const float*)d_in[14];
    const float* be2 = (const float*)d_in[15];
    const float* Wl1 = (const float*)d_in[16];
    const float* bl1 = (const float*)d_in[17];
    const float* Wl2 = (const float*)d_in[18];
    const float* bl2 = (const float*)d_in[19];
    float* out = (float*)d_out;

    float *ph1, *ph2;
    void *pst, *pdt, *pdc;
    cudaGetSymbolAddress((void**)&ph1, g_h1);
    cudaGetSymbolAddress((void**)&ph2, g_h2);
    cudaGetSymbolAddress(&pst, g_srct);
    cudaGetSymbolAddress(&pdt, g_dstt);
    cudaGetSymbolAddress(&pdc, g_dc);

    int nblk = (NN + 7) / 8;          // warp-per-node kernels
    int wblk = (NN + 127) / 128;      // WMMA kernels (128 nodes/block)

    cudaMemsetAsync(pdc, 0, NN * sizeof(int));
    // fused: p1 projection + degree histogram (independent work, one launch)
    k_dp<<<PROJ_B + DEG_B, 256>>>(dst, node_feat, W1n);
    k_scan1<<<NB_SCAN, 1024>>>();
    k_scan3<<<(NN + 255) / 256, 256>>>();   // fuses bsum-scan + finalize + inv + cursor
    k_scatter<<<(NE + 255) / 256, 256>>>(src, dst);

    // Layer 1
    k_sage1<<<nblk, 256>>>(node_feat, W1s, b1);

    // Layer 2: p2 = h1@W2n (half2) AND h1@W2s (fp32) via WMMA, then combine
    k_wdual<<<wblk, 256>>>(ph1, W2n, W2s, ph2);
    k_sage2b<<<nblk, 256>>>(b2);

    // fused: hp = relu(h2@Wnp+bnp) in smem, then both role tables
    k_wfuse<<<wblk, 256>>>(ph2, Wnp, bnp, We1, Wl1,
                           (unsigned int*)pst, (unsigned int*)pdt);

    // persistent fused edge stage: 8 lanes/edge, 4 edges/warp, 2-deep pipeline
    k_edge<<<592, 256>>>(src, dst, edge_feat,
                         We1, be1, We2, be2, Wl1, bl1, Wl2, bl2, out);
}